// round 7
// baseline (speedup 1.0000x reference)
#include <cuda_runtime.h>
#include <math.h>

typedef unsigned long long u64;

#define B_  2
#define S_  2048
#define D_  1024
#define H_  16
#define HD_ 64
#define M_  (B_ * S_)   // 4096

// Scratch (device globals; allocation is forbidden).
__device__ float g_q[B_ * H_ * S_ * HD_];
__device__ float g_k[B_ * H_ * S_ * HD_];
__device__ float g_v[B_ * H_ * S_ * HD_];
__device__ float g_ctx[B_ * S_ * D_];

// ---- packed fp32x2 helpers (FFMA2 path: only reachable via PTX) -----------
__device__ __forceinline__ u64 splat2(float x) {
    u64 r; asm("mov.b64 %0, {%1, %1};" : "=l"(r) : "f"(x)); return r;
}
__device__ __forceinline__ void ffma2(u64& d, u64 a, u64 b) {
    asm("fma.rn.f32x2 %0, %1, %2, %0;" : "+l"(d) : "l"(a), "l"(b));
}
__device__ __forceinline__ u64 fmul2(u64 a, u64 b) {
    u64 r; asm("mul.rn.f32x2 %0, %1, %2;" : "=l"(r) : "l"(a), "l"(b)); return r;
}
__device__ __forceinline__ float2 unpack2(u64 v) {
    float2 r; asm("mov.b64 {%0, %1}, %2;" : "=f"(r.x), "=f"(r.y) : "l"(v)); return r;
}

// ---------------------------------------------------------------------------
// Tiled SGEMM with FFMA2: C[M,1024] = A[M,1024] @ W[1024,1024] + bias
// BM=BN=128, BK=16, 256 threads, 8x8 register tile per thread (as 8x4 f32x2).
// A tile stored PRE-SPLATTED in smem (u64 with both halves equal) so the
// inner loop is pure LDS.128 + FFMA2.
// QKV=true: gridDim.z selects among 3 weight sets (fused QKV projection).
// SPLIT=true: write head-split layout [B,H,S,HD]; else plain row-major.
// ---------------------------------------------------------------------------
template <bool SPLIT, bool QKV>
__global__ __launch_bounds__(256) void gemm_kernel(
    const float* __restrict__ A,
    const float* __restrict__ Wa, const float* __restrict__ ba, float* __restrict__ oa,
    const float* __restrict__ Wb, const float* __restrict__ bb, float* __restrict__ ob,
    const float* __restrict__ Wc, const float* __restrict__ bc, float* __restrict__ oc)
{
    const float* W = Wa; const float* bias = ba; float* out = oa;
    if (QKV) {
        int z = blockIdx.z;
        if (z == 1) { W = Wb; bias = bb; out = ob; }
        if (z == 2) { W = Wc; bias = bc; out = oc; }
    }

    __shared__ u64   As2[16][128];   // A tile transposed + splatted: As2[k][m]
    __shared__ float Bs[16][128];    // W tile: Bs[k][n]

    const int t    = threadIdx.x;
    const int tx   = t & 15;
    const int ty   = t >> 4;
    const int n0   = blockIdx.x * 128;
    const int row0 = blockIdx.y * 128;

    u64 acc[8][4];
#pragma unroll
    for (int i = 0; i < 8; i++)
#pragma unroll
        for (int j = 0; j < 4; j++) acc[i][j] = 0ull;

    for (int k0 = 0; k0 < D_; k0 += 16) {
#pragma unroll
        for (int l = 0; l < 2; l++) {
            int idx = t + l * 256;
            int ar = idx >> 2, ac4 = idx & 3;
            float4 a4 = *(const float4*)&A[(size_t)(row0 + ar) * D_ + k0 + ac4 * 4];
            As2[ac4 * 4 + 0][ar] = splat2(a4.x);
            As2[ac4 * 4 + 1][ar] = splat2(a4.y);
            As2[ac4 * 4 + 2][ar] = splat2(a4.z);
            As2[ac4 * 4 + 3][ar] = splat2(a4.w);
            int kr = idx >> 5, bc4 = idx & 31;
            *(float4*)&Bs[kr][bc4 * 4] =
                *(const float4*)&W[(size_t)(k0 + kr) * D_ + n0 + bc4 * 4];
        }
        __syncthreads();

#pragma unroll
        for (int k = 0; k < 16; k++) {
            u64 a2[8], b2[4];
            ulonglong2 p;
            p = *(const ulonglong2*)&As2[k][ty * 8 + 0]; a2[0] = p.x; a2[1] = p.y;
            p = *(const ulonglong2*)&As2[k][ty * 8 + 2]; a2[2] = p.x; a2[3] = p.y;
            p = *(const ulonglong2*)&As2[k][ty * 8 + 4]; a2[4] = p.x; a2[5] = p.y;
            p = *(const ulonglong2*)&As2[k][ty * 8 + 6]; a2[6] = p.x; a2[7] = p.y;
            ulonglong2 q0v = *(const ulonglong2*)&Bs[k][tx * 8];
            ulonglong2 q1v = *(const ulonglong2*)&Bs[k][tx * 8 + 4];
            b2[0] = q0v.x; b2[1] = q0v.y; b2[2] = q1v.x; b2[3] = q1v.y;
#pragma unroll
            for (int i = 0; i < 8; i++)
#pragma unroll
                for (int j = 0; j < 4; j++)
                    ffma2(acc[i][j], a2[i], b2[j]);
        }
        __syncthreads();
    }

#pragma unroll
    for (int i = 0; i < 8; i++) {
        int row = row0 + ty * 8 + i;
#pragma unroll
        for (int j = 0; j < 4; j++) {
            int col = n0 + tx * 8 + j * 2;
            float2 v = unpack2(acc[i][j]);
            v.x += bias[col];
            v.y += bias[col + 1];
            if (SPLIT) {
                int b = row >> 11;
                int s = row & (S_ - 1);
                int h = col >> 6;
                int hd = col & 63;
                *(float2*)&out[(((size_t)(b * H_ + h)) * S_ + s) * HD_ + hd] = v;
            } else {
                *(float2*)&out[(size_t)row * D_ + col] = v;
            }
        }
    }
}

// ---------------------------------------------------------------------------
// Flash-attention with FFMA2. Block = 64 queries of one (b,h); 256 threads as
// 16x16, 4x4 micro-tile (stored as 4x2 f32x2). Q and P held pre-splatted in
// smem; K transposed + XOR-swizzled; pairing along keys (QK) / dims (PV).
// Dynamic smem: Qs2[64][66]u64 + Ps2/Kt[64][66]u64 + Vs[64][68]f = 84992 B.
// ---------------------------------------------------------------------------
__global__ __launch_bounds__(256) void attn_kernel()
{
    extern __shared__ char smraw[];
    u64*   Qs2 = (u64*)smraw;              // [64][66] splatted Q (pre-scaled)
    u64*   Ps2 = Qs2 + 64 * 66;            // [64][66] splatted P (aliases Ktf)
    float* Ktf = (float*)Ps2;              // [64 d][64 key] swizzled
    float* Vs  = (float*)(Ps2 + 64 * 66);  // [64][68]

    const int t  = threadIdx.x;
    const int tx = t & 15;
    const int ty = t >> 4;
    const int q0 = blockIdx.x * 64;
    const int bh = blockIdx.y;
    const size_t base = (size_t)bh * S_ * HD_;
    const float* Qg = g_q + base;
    const float* Kg = g_k + base;
    const float* Vg = g_v + base;

    // Q tile, pre-scaled by 1/sqrt(64) and splatted
#pragma unroll
    for (int l = 0; l < 4; l++) {
        int idx = t + l * 256;
        int r = idx >> 4, c4 = idx & 15;
        float4 v = *(const float4*)&Qg[(size_t)(q0 + r) * HD_ + c4 * 4];
        u64* dst = &Qs2[r * 66 + c4 * 4];
        dst[0] = splat2(v.x * 0.125f);
        dst[1] = splat2(v.y * 0.125f);
        dst[2] = splat2(v.z * 0.125f);
        dst[3] = splat2(v.w * 0.125f);
    }

    float m_i[4], l_i[4];
    u64 o2[4][2];
#pragma unroll
    for (int i = 0; i < 4; i++) {
        m_i[i] = -1e30f; l_i[i] = 0.f;
        o2[i][0] = 0ull; o2[i][1] = 0ull;
    }
    __syncthreads();

    for (int kt = 0; kt < S_ / 64; kt++) {
        const int k0 = kt * 64;
#pragma unroll
        for (int l = 0; l < 4; l++) {
            int idx = t + l * 256;
            int r = idx >> 4, c4 = idx & 15;
            float4 kv = *(const float4*)&Kg[(size_t)(k0 + r) * HD_ + c4 * 4];
            int pos = (((r >> 2) ^ c4) << 2) + (r & 3);
            Ktf[(c4 * 4 + 0) * 64 + pos] = kv.x;
            Ktf[(c4 * 4 + 1) * 64 + pos] = kv.y;
            Ktf[(c4 * 4 + 2) * 64 + pos] = kv.z;
            Ktf[(c4 * 4 + 3) * 64 + pos] = kv.w;
            *(float4*)&Vs[r * 68 + c4 * 4] =
                *(const float4*)&Vg[(size_t)(k0 + r) * HD_ + c4 * 4];
        }
        __syncthreads();

        // S = Q @ K^T  — keys paired: s2[i][jj] holds keys (tx*4+2jj, +2jj+1)
        u64 s2[4][2];
#pragma unroll
        for (int i = 0; i < 4; i++) { s2[i][0] = 0ull; s2[i][1] = 0ull; }

#pragma unroll
        for (int dd = 0; dd < 64; dd += 4) {
            int sw = ((tx ^ (dd >> 2)) << 2);
            ulonglong2 kb0 = *(const ulonglong2*)&Ktf[(dd + 0) * 64 + sw];
            ulonglong2 kb1 = *(const ulonglong2*)&Ktf[(dd + 1) * 64 + sw];
            ulonglong2 kb2 = *(const ulonglong2*)&Ktf[(dd + 2) * 64 + sw];
            ulonglong2 kb3 = *(const ulonglong2*)&Ktf[(dd + 3) * 64 + sw];
#pragma unroll
            for (int i = 0; i < 4; i++) {
                const u64* qr = &Qs2[(ty * 4 + i) * 66 + dd];
                ulonglong2 a01 = *(const ulonglong2*)&qr[0];
                ulonglong2 a23 = *(const ulonglong2*)&qr[2];
                ffma2(s2[i][0], a01.x, kb0.x); ffma2(s2[i][1], a01.x, kb0.y);
                ffma2(s2[i][0], a01.y, kb1.x); ffma2(s2[i][1], a01.y, kb1.y);
                ffma2(s2[i][0], a23.x, kb2.x); ffma2(s2[i][1], a23.x, kb2.y);
                ffma2(s2[i][0], a23.y, kb3.x); ffma2(s2[i][1], a23.y, kb3.y);
            }
        }
        __syncthreads();   // all Ktf reads done before P overwrites it

        // Online softmax (row group = 16 lanes; width-16 shfl reductions)
        float p[4][4];
#pragma unroll
        for (int i = 0; i < 4; i++) {
            float2 u0 = unpack2(s2[i][0]);
            float2 u1 = unpack2(s2[i][1]);
            p[i][0] = u0.x; p[i][1] = u0.y; p[i][2] = u1.x; p[i][3] = u1.y;
            float mx = fmaxf(fmaxf(p[i][0], p[i][1]), fmaxf(p[i][2], p[i][3]));
            mx = fmaxf(mx, __shfl_xor_sync(0xffffffffu, mx, 1));
            mx = fmaxf(mx, __shfl_xor_sync(0xffffffffu, mx, 2));
            mx = fmaxf(mx, __shfl_xor_sync(0xffffffffu, mx, 4));
            mx = fmaxf(mx, __shfl_xor_sync(0xffffffffu, mx, 8));
            float mnew = fmaxf(m_i[i], mx);
            float corr = __expf(m_i[i] - mnew);
            float rs = 0.f;
#pragma unroll
            for (int j = 0; j < 4; j++) {
                p[i][j] = __expf(p[i][j] - mnew);
                rs += p[i][j];
            }
            rs += __shfl_xor_sync(0xffffffffu, rs, 1);
            rs += __shfl_xor_sync(0xffffffffu, rs, 2);
            rs += __shfl_xor_sync(0xffffffffu, rs, 4);
            rs += __shfl_xor_sync(0xffffffffu, rs, 8);
            l_i[i] = l_i[i] * corr + rs;
            m_i[i] = mnew;
            u64 c2 = splat2(corr);
            o2[i][0] = fmul2(o2[i][0], c2);
            o2[i][1] = fmul2(o2[i][1], c2);
        }

        // P -> smem, splatted
#pragma unroll
        for (int i = 0; i < 4; i++) {
            u64* dst = &Ps2[(ty * 4 + i) * 66 + tx * 4];
            ulonglong2 w0, w1;
            w0.x = splat2(p[i][0]); w0.y = splat2(p[i][1]);
            w1.x = splat2(p[i][2]); w1.y = splat2(p[i][3]);
            *(ulonglong2*)&dst[0] = w0;
            *(ulonglong2*)&dst[2] = w1;
        }
        __syncthreads();

        // O += P @ V  — dims paired: o2[i][jj] holds dims (tx*4+2jj, +2jj+1)
#pragma unroll
        for (int kk = 0; kk < 64; kk += 4) {
            ulonglong2 v0 = *(const ulonglong2*)&Vs[(kk + 0) * 68 + tx * 4];
            ulonglong2 v1 = *(const ulonglong2*)&Vs[(kk + 1) * 68 + tx * 4];
            ulonglong2 v2 = *(const ulonglong2*)&Vs[(kk + 2) * 68 + tx * 4];
            ulonglong2 v3 = *(const ulonglong2*)&Vs[(kk + 3) * 68 + tx * 4];
#pragma unroll
            for (int i = 0; i < 4; i++) {
                const u64* pr = &Ps2[(ty * 4 + i) * 66 + kk];
                ulonglong2 p01 = *(const ulonglong2*)&pr[0];
                ulonglong2 p23 = *(const ulonglong2*)&pr[2];
                ffma2(o2[i][0], p01.x, v0.x); ffma2(o2[i][1], p01.x, v0.y);
                ffma2(o2[i][0], p01.y, v1.x); ffma2(o2[i][1], p01.y, v1.y);
                ffma2(o2[i][0], p23.x, v2.x); ffma2(o2[i][1], p23.x, v2.y);
                ffma2(o2[i][0], p23.y, v3.x); ffma2(o2[i][1], p23.y, v3.y);
            }
        }
        __syncthreads();   // before next tile overwrites Ktf/Vs
    }

    // ctx[b, s, h*64 + d] = O / l
    const int b = bh >> 4;
    const int h = bh & 15;
#pragma unroll
    for (int i = 0; i < 4; i++) {
        float inv = 1.f / l_i[i];
        float2 a = unpack2(o2[i][0]);
        float2 c = unpack2(o2[i][1]);
        int srow = q0 + ty * 4 + i;
        *(float4*)&g_ctx[((size_t)(b * S_ + srow)) * D_ + h * HD_ + tx * 4] =
            make_float4(a.x * inv, a.y * inv, c.x * inv, c.y * inv);
    }
}

// ---------------------------------------------------------------------------

extern "C" void kernel_launch(void* const* d_in, const int* in_sizes, int n_in,
                              void* d_out, int out_size)
{
    const float* x  = (const float*)d_in[0];
    const float* Wq = (const float*)d_in[1];
    const float* bq = (const float*)d_in[2];
    const float* Wk = (const float*)d_in[3];
    const float* bk = (const float*)d_in[4];
    const float* Wv = (const float*)d_in[5];
    const float* bv = (const float*)d_in[6];
    const float* Wo = (const float*)d_in[7];
    const float* bo = (const float*)d_in[8];
    float* out = (float*)d_out;

    float *qp, *kp, *vp, *cp;
    cudaGetSymbolAddress((void**)&qp, g_q);
    cudaGetSymbolAddress((void**)&kp, g_k);
    cudaGetSymbolAddress((void**)&vp, g_v);
    cudaGetSymbolAddress((void**)&cp, g_ctx);

    const int ATTN_SMEM = 2 * 64 * 66 * 8 + 64 * 68 * 4;   // 84992 B
    cudaFuncSetAttribute(attn_kernel,
                         cudaFuncAttributeMaxDynamicSharedMemorySize, ATTN_SMEM);

    dim3 gg(D_ / 128, M_ / 128);   // (8, 32)

    // Fused Q/K/V projection: z selects weight set
    gemm_kernel<true, true><<<dim3(8, 32, 3), 256>>>(
        x, Wq, bq, qp, Wk, bk, kp, Wv, bv, vp);

    attn_kernel<<<dim3(S_ / 64, B_ * H_), 256, ATTN_SMEM>>>();

    gemm_kernel<false, false><<<gg, 256>>>(
        cp, Wo, bo, out, nullptr, nullptr, nullptr, nullptr, nullptr, nullptr);
}

// round 11
// speedup vs baseline: 1.0433x; 1.0433x over previous
#include <cuda_runtime.h>
#include <math.h>

typedef unsigned long long u64;

#define B_  2
#define S_  2048
#define D_  1024
#define H_  16
#define HD_ 64
#define M_  (B_ * S_)   // 4096

// Scratch (device globals; allocation is forbidden).
__device__ float g_q[B_ * H_ * S_ * HD_];
__device__ float g_k[B_ * H_ * S_ * HD_];
__device__ float g_v[B_ * H_ * S_ * HD_];
__device__ float g_ctx[B_ * S_ * D_];

// ---- packed fp32x2 helpers (FFMA2 path: only reachable via PTX) -----------
__device__ __forceinline__ u64 splat2(float x) {
    u64 r; asm("mov.b64 %0, {%1, %1};" : "=l"(r) : "f"(x)); return r;
}
__device__ __forceinline__ void ffma2(u64& d, u64 a, u64 b) {
    asm("fma.rn.f32x2 %0, %1, %2, %0;" : "+l"(d) : "l"(a), "l"(b));
}
__device__ __forceinline__ u64 fmul2(u64 a, u64 b) {
    u64 r; asm("mul.rn.f32x2 %0, %1, %2;" : "=l"(r) : "l"(a), "l"(b)); return r;
}
__device__ __forceinline__ float2 unpack2(u64 v) {
    float2 r; asm("mov.b64 {%0, %1}, %2;" : "=f"(r.x), "=f"(r.y) : "l"(v)); return r;
}

// ---------------------------------------------------------------------------
// Tiled SGEMM with FFMA2: C[M,1024] = A[M,1024] @ W[1024,1024] + bias
// BM=BN=128, BK=16, 256 threads, 8x8 register tile per thread (as 8x4 f32x2).
// A tile PRE-SPLATTED in smem; inner loop = LDS.128 + FFMA2 with minimal
// operand live-range (B cached, A loaded per row-pair).
// __launch_bounds__(256,2) caps regs at 128 -> 2 CTAs/SM (R7 lesson: 146 regs
// -> 1 CTA/SM -> issue 29.8%).
// ---------------------------------------------------------------------------
template <bool SPLIT, bool QKV>
__global__ __launch_bounds__(256, 2) void gemm_kernel(
    const float* __restrict__ A,
    const float* __restrict__ Wa, const float* __restrict__ ba, float* __restrict__ oa,
    const float* __restrict__ Wb, const float* __restrict__ bb, float* __restrict__ ob,
    const float* __restrict__ Wc, const float* __restrict__ bc, float* __restrict__ oc)
{
    const float* W = Wa; const float* bias = ba; float* out = oa;
    if (QKV) {
        int z = blockIdx.z;
        if (z == 1) { W = Wb; bias = bb; out = ob; }
        if (z == 2) { W = Wc; bias = bc; out = oc; }
    }

    __shared__ u64   As2[16][128];   // A tile transposed + splatted: As2[k][m]
    __shared__ float Bs[16][128];    // W tile: Bs[k][n]

    const int t    = threadIdx.x;
    const int tx   = t & 15;
    const int ty   = t >> 4;
    const int n0   = blockIdx.x * 128;
    const int row0 = blockIdx.y * 128;

    u64 acc[8][4];
#pragma unroll
    for (int i = 0; i < 8; i++)
#pragma unroll
        for (int j = 0; j < 4; j++) acc[i][j] = 0ull;

    for (int k0 = 0; k0 < D_; k0 += 16) {
#pragma unroll
        for (int l = 0; l < 2; l++) {
            int idx = t + l * 256;
            int ar = idx >> 2, ac4 = idx & 3;
            float4 a4 = *(const float4*)&A[(size_t)(row0 + ar) * D_ + k0 + ac4 * 4];
            As2[ac4 * 4 + 0][ar] = splat2(a4.x);
            As2[ac4 * 4 + 1][ar] = splat2(a4.y);
            As2[ac4 * 4 + 2][ar] = splat2(a4.z);
            As2[ac4 * 4 + 3][ar] = splat2(a4.w);
            int kr = idx >> 5, bc4 = idx & 31;
            *(float4*)&Bs[kr][bc4 * 4] =
                *(const float4*)&W[(size_t)(k0 + kr) * D_ + n0 + bc4 * 4];
        }
        __syncthreads();

#pragma unroll
        for (int k = 0; k < 16; k++) {
            // Cache only the 4 B-operand u64s; load A pairs just-in-time.
            ulonglong2 b01 = *(const ulonglong2*)&Bs[k][tx * 8];
            ulonglong2 b23 = *(const ulonglong2*)&Bs[k][tx * 8 + 4];
#pragma unroll
            for (int ii = 0; ii < 4; ii++) {
                ulonglong2 aa = *(const ulonglong2*)&As2[k][ty * 8 + ii * 2];
                ffma2(acc[2 * ii + 0][0], aa.x, b01.x);
                ffma2(acc[2 * ii + 0][1], aa.x, b01.y);
                ffma2(acc[2 * ii + 0][2], aa.x, b23.x);
                ffma2(acc[2 * ii + 0][3], aa.x, b23.y);
                ffma2(acc[2 * ii + 1][0], aa.y, b01.x);
                ffma2(acc[2 * ii + 1][1], aa.y, b01.y);
                ffma2(acc[2 * ii + 1][2], aa.y, b23.x);
                ffma2(acc[2 * ii + 1][3], aa.y, b23.y);
            }
        }
        __syncthreads();
    }

#pragma unroll
    for (int i = 0; i < 8; i++) {
        int row = row0 + ty * 8 + i;
#pragma unroll
        for (int j = 0; j < 4; j++) {
            int col = n0 + tx * 8 + j * 2;
            float2 v = unpack2(acc[i][j]);
            v.x += bias[col];
            v.y += bias[col + 1];
            if (SPLIT) {
                int b = row >> 11;
                int s = row & (S_ - 1);
                int h = col >> 6;
                int hd = col & 63;
                *(float2*)&out[(((size_t)(b * H_ + h)) * S_ + s) * HD_ + hd] = v;
            } else {
                *(float2*)&out[(size_t)row * D_ + col] = v;
            }
        }
    }
}

// ---------------------------------------------------------------------------
// Flash-attention with FFMA2. Block = 64 queries of one (b,h); 256 threads as
// 16x16, 4x4 micro-tile (stored as 4x2 f32x2). Q and P pre-splatted in smem;
// K transposed + XOR-swizzled. __launch_bounds__(256,2) caps regs at 128
// (smem 84992B already limits to 2 CTAs/SM; regs must not limit further).
// ---------------------------------------------------------------------------
__global__ __launch_bounds__(256, 2) void attn_kernel()
{
    extern __shared__ char smraw[];
    u64*   Qs2 = (u64*)smraw;              // [64][66] splatted Q (pre-scaled)
    u64*   Ps2 = Qs2 + 64 * 66;            // [64][66] splatted P (aliases Ktf)
    float* Ktf = (float*)Ps2;              // [64 d][64 key] swizzled
    float* Vs  = (float*)(Ps2 + 64 * 66);  // [64][68]

    const int t  = threadIdx.x;
    const int tx = t & 15;
    const int ty = t >> 4;
    const int q0 = blockIdx.x * 64;
    const int bh = blockIdx.y;
    const size_t base = (size_t)bh * S_ * HD_;
    const float* Qg = g_q + base;
    const float* Kg = g_k + base;
    const float* Vg = g_v + base;

    // Q tile, pre-scaled by 1/sqrt(64) and splatted
#pragma unroll
    for (int l = 0; l < 4; l++) {
        int idx = t + l * 256;
        int r = idx >> 4, c4 = idx & 15;
        float4 v = *(const float4*)&Qg[(size_t)(q0 + r) * HD_ + c4 * 4];
        u64* dst = &Qs2[r * 66 + c4 * 4];
        dst[0] = splat2(v.x * 0.125f);
        dst[1] = splat2(v.y * 0.125f);
        dst[2] = splat2(v.z * 0.125f);
        dst[3] = splat2(v.w * 0.125f);
    }

    float m_i[4], l_i[4];
    u64 o2[4][2];
#pragma unroll
    for (int i = 0; i < 4; i++) {
        m_i[i] = -1e30f; l_i[i] = 0.f;
        o2[i][0] = 0ull; o2[i][1] = 0ull;
    }
    __syncthreads();

    for (int kt = 0; kt < S_ / 64; kt++) {
        const int k0 = kt * 64;
#pragma unroll
        for (int l = 0; l < 4; l++) {
            int idx = t + l * 256;
            int r = idx >> 4, c4 = idx & 15;
            float4 kv = *(const float4*)&Kg[(size_t)(k0 + r) * HD_ + c4 * 4];
            int pos = (((r >> 2) ^ c4) << 2) + (r & 3);
            Ktf[(c4 * 4 + 0) * 64 + pos] = kv.x;
            Ktf[(c4 * 4 + 1) * 64 + pos] = kv.y;
            Ktf[(c4 * 4 + 2) * 64 + pos] = kv.z;
            Ktf[(c4 * 4 + 3) * 64 + pos] = kv.w;
            *(float4*)&Vs[r * 68 + c4 * 4] =
                *(const float4*)&Vg[(size_t)(k0 + r) * HD_ + c4 * 4];
        }
        __syncthreads();

        // S = Q @ K^T  — keys paired: s2[i][jj] holds keys (tx*4+2jj, +2jj+1)
        u64 s2[4][2];
#pragma unroll
        for (int i = 0; i < 4; i++) { s2[i][0] = 0ull; s2[i][1] = 0ull; }

#pragma unroll
        for (int dd = 0; dd < 64; dd += 4) {
            int sw = ((tx ^ (dd >> 2)) << 2);
            ulonglong2 kb0 = *(const ulonglong2*)&Ktf[(dd + 0) * 64 + sw];
            ulonglong2 kb1 = *(const ulonglong2*)&Ktf[(dd + 1) * 64 + sw];
            ulonglong2 kb2 = *(const ulonglong2*)&Ktf[(dd + 2) * 64 + sw];
            ulonglong2 kb3 = *(const ulonglong2*)&Ktf[(dd + 3) * 64 + sw];
#pragma unroll
            for (int i = 0; i < 4; i++) {
                const u64* qr = &Qs2[(ty * 4 + i) * 66 + dd];
                ulonglong2 a01 = *(const ulonglong2*)&qr[0];
                ulonglong2 a23 = *(const ulonglong2*)&qr[2];
                ffma2(s2[i][0], a01.x, kb0.x); ffma2(s2[i][1], a01.x, kb0.y);
                ffma2(s2[i][0], a01.y, kb1.x); ffma2(s2[i][1], a01.y, kb1.y);
                ffma2(s2[i][0], a23.x, kb2.x); ffma2(s2[i][1], a23.x, kb2.y);
                ffma2(s2[i][0], a23.y, kb3.x); ffma2(s2[i][1], a23.y, kb3.y);
            }
        }
        __syncthreads();   // all Ktf reads done before P overwrites it

        // Online softmax (row group = 16 lanes; width-16 shfl reductions)
        float p[4][4];
#pragma unroll
        for (int i = 0; i < 4; i++) {
            float2 u0 = unpack2(s2[i][0]);
            float2 u1 = unpack2(s2[i][1]);
            p[i][0] = u0.x; p[i][1] = u0.y; p[i][2] = u1.x; p[i][3] = u1.y;
            float mx = fmaxf(fmaxf(p[i][0], p[i][1]), fmaxf(p[i][2], p[i][3]));
            mx = fmaxf(mx, __shfl_xor_sync(0xffffffffu, mx, 1));
            mx = fmaxf(mx, __shfl_xor_sync(0xffffffffu, mx, 2));
            mx = fmaxf(mx, __shfl_xor_sync(0xffffffffu, mx, 4));
            mx = fmaxf(mx, __shfl_xor_sync(0xffffffffu, mx, 8));
            float mnew = fmaxf(m_i[i], mx);
            float corr = __expf(m_i[i] - mnew);
            float rs = 0.f;
#pragma unroll
            for (int j = 0; j < 4; j++) {
                p[i][j] = __expf(p[i][j] - mnew);
                rs += p[i][j];
            }
            rs += __shfl_xor_sync(0xffffffffu, rs, 1);
            rs += __shfl_xor_sync(0xffffffffu, rs, 2);
            rs += __shfl_xor_sync(0xffffffffu, rs, 4);
            rs += __shfl_xor_sync(0xffffffffu, rs, 8);
            l_i[i] = l_i[i] * corr + rs;
            m_i[i] = mnew;
            u64 c2 = splat2(corr);
            o2[i][0] = fmul2(o2[i][0], c2);
            o2[i][1] = fmul2(o2[i][1], c2);
        }

        // P -> smem, splatted
#pragma unroll
        for (int i = 0; i < 4; i++) {
            u64* dst = &Ps2[(ty * 4 + i) * 66 + tx * 4];
            ulonglong2 w0, w1;
            w0.x = splat2(p[i][0]); w0.y = splat2(p[i][1]);
            w1.x = splat2(p[i][2]); w1.y = splat2(p[i][3]);
            *(ulonglong2*)&dst[0] = w0;
            *(ulonglong2*)&dst[2] = w1;
        }
        __syncthreads();

        // O += P @ V  — dims paired: o2[i][jj] holds dims (tx*4+2jj, +2jj+1)
#pragma unroll
        for (int kk = 0; kk < 64; kk += 4) {
            ulonglong2 v0 = *(const ulonglong2*)&Vs[(kk + 0) * 68 + tx * 4];
            ulonglong2 v1 = *(const ulonglong2*)&Vs[(kk + 1) * 68 + tx * 4];
            ulonglong2 v2 = *(const ulonglong2*)&Vs[(kk + 2) * 68 + tx * 4];
            ulonglong2 v3 = *(const ulonglong2*)&Vs[(kk + 3) * 68 + tx * 4];
#pragma unroll
            for (int i = 0; i < 4; i++) {
                const u64* pr = &Ps2[(ty * 4 + i) * 66 + kk];
                ulonglong2 p01 = *(const ulonglong2*)&pr[0];
                ulonglong2 p23 = *(const ulonglong2*)&pr[2];
                ffma2(o2[i][0], p01.x, v0.x); ffma2(o2[i][1], p01.x, v0.y);
                ffma2(o2[i][0], p01.y, v1.x); ffma2(o2[i][1], p01.y, v1.y);
                ffma2(o2[i][0], p23.x, v2.x); ffma2(o2[i][1], p23.x, v2.y);
                ffma2(o2[i][0], p23.y, v3.x); ffma2(o2[i][1], p23.y, v3.y);
            }
        }
        __syncthreads();   // before next tile overwrites Ktf/Vs
    }

    // ctx[b, s, h*64 + d] = O / l
    const int b = bh >> 4;
    const int h = bh & 15;
#pragma unroll
    for (int i = 0; i < 4; i++) {
        float inv = 1.f / l_i[i];
        float2 a = unpack2(o2[i][0]);
        float2 c = unpack2(o2[i][1]);
        int srow = q0 + ty * 4 + i;
        *(float4*)&g_ctx[((size_t)(b * S_ + srow)) * D_ + h * HD_ + tx * 4] =
            make_float4(a.x * inv, a.y * inv, c.x * inv, c.y * inv);
    }
}

// ---------------------------------------------------------------------------

extern "C" void kernel_launch(void* const* d_in, const int* in_sizes, int n_in,
                              void* d_out, int out_size)
{
    const float* x  = (const float*)d_in[0];
    const float* Wq = (const float*)d_in[1];
    const float* bq = (const float*)d_in[2];
    const float* Wk = (const float*)d_in[3];
    const float* bk = (const float*)d_in[4];
    const float* Wv = (const float*)d_in[5];
    const float* bv = (const float*)d_in[6];
    const float* Wo = (const float*)d_in[7];
    const float* bo = (const float*)d_in[8];
    float* out = (float*)d_out;

    float *qp, *kp, *vp, *cp;
    cudaGetSymbolAddress((void**)&qp, g_q);
    cudaGetSymbolAddress((void**)&kp, g_k);
    cudaGetSymbolAddress((void**)&vp, g_v);
    cudaGetSymbolAddress((void**)&cp, g_ctx);

    const int ATTN_SMEM = 2 * 64 * 66 * 8 + 64 * 68 * 4;   // 84992 B
    cudaFuncSetAttribute(attn_kernel,
                         cudaFuncAttributeMaxDynamicSharedMemorySize, ATTN_SMEM);

    dim3 gg(D_ / 128, M_ / 128);   // (8, 32)

    // Fused Q/K/V projection: z selects weight set
    gemm_kernel<true, true><<<dim3(8, 32, 3), 256>>>(
        x, Wq, bq, qp, Wk, bk, kp, Wv, bv, vp);

    attn_kernel<<<dim3(S_ / 64, B_ * H_), 256, ATTN_SMEM>>>();

    gemm_kernel<false, false><<<gg, 256>>>(
        cp, Wo, bo, out, nullptr, nullptr, nullptr, nullptr, nullptr, nullptr);
}